// round 15
// baseline (speedup 1.0000x reference)
#include <cuda_runtime.h>
#include <math.h>
#include <cstdint>

typedef uint32_t u32;

// Problem constants
#define Bn 2
#define Sn 2048
#define En 1024
#define Hn 16
#define Dn 64
#define Mn (Bn*Sn)   // 4096 rows
#define MEG (1 << 20)

// Scratch (static __device__ arrays: allocation-guard safe)
__device__ float g_Q[Bn*Hn*Sn*Dn];   // [B,H,S,D]
__device__ float g_K[Bn*Hn*Sn*Dn];
__device__ float g_V[Bn*Hn*Sn*Dn];
__device__ float g_maskf[Bn*Sn];     // normalized mask: 1.0 = masked out
// bf16 split planes
__device__ unsigned short g_Xh[Mn*En], g_Xl[Mn*En];      // x split
__device__ unsigned short g_Wh[4*En*En], g_Wl[4*En*En];  // Wq,Wk,Wv,Wo split
__device__ unsigned short g_Ahb[Mn*En], g_Alb[Mn*En];    // attn out split
__device__ unsigned short g_Kbh[Bn*Hn*Sn*Dn], g_Kbl[Bn*Hn*Sn*Dn];  // K split
__device__ unsigned short g_Vth[Bn*Hn*Dn*Sn], g_Vtl[Bn*Hn*Dn*Sn];  // V^T split

// ===========================================================================
// helpers
// ===========================================================================
__device__ __forceinline__ void bsplit(float x, u32& h, u32& l) {
    u32 u = __float_as_uint(x);
    h = u >> 16;
    float lo = x - __uint_as_float(u & 0xFFFF0000u);
    l = __float_as_uint(lo) >> 16;
}
__device__ __forceinline__ void psplit2(float x, float y, u32& hp, u32& lp) {
    u32 ux = __float_as_uint(x), uy = __float_as_uint(y);
    float xl = x - __uint_as_float(ux & 0xFFFF0000u);
    float yl = y - __uint_as_float(uy & 0xFFFF0000u);
    hp = (ux >> 16) | (uy & 0xFFFF0000u);
    lp = (__float_as_uint(xl) >> 16) | (__float_as_uint(yl) & 0xFFFF0000u);
}
__device__ __forceinline__ void mma_bf16(float* c, u32 a0, u32 a1,
                                         u32 a2, u32 a3, u32 b0, u32 b1) {
    asm volatile(
        "mma.sync.aligned.m16n8k16.row.col.f32.bf16.bf16.f32 "
        "{%0,%1,%2,%3}, {%4,%5,%6,%7}, {%8,%9}, {%0,%1,%2,%3};"
        : "+f"(c[0]), "+f"(c[1]), "+f"(c[2]), "+f"(c[3])
        : "r"(a0), "r"(a1), "r"(a2), "r"(a3), "r"(b0), "r"(b1));
}
__device__ __forceinline__ u32 smem_u32(const void* p) {
    u32 a;
    asm("{ .reg .u64 t; cvta.to.shared.u64 t, %1; cvt.u32.u64 %0, t; }"
        : "=r"(a) : "l"(p));
    return a;
}
#define LDSM_X4(r0, r1, r2, r3, addr) \
    asm volatile("ldmatrix.sync.aligned.m8n8.x4.shared.b16 {%0,%1,%2,%3}, [%4];" \
        : "=r"(r0), "=r"(r1), "=r"(r2), "=r"(r3) : "r"(addr))
#define CP_ASYNC16(dst, src) \
    asm volatile("cp.async.cg.shared.global [%0], [%1], 16;" \
                 :: "r"(dst), "l"(src) : "memory")
#define CP_COMMIT() asm volatile("cp.async.commit_group;" ::: "memory")
#define CP_WAIT0()  asm volatile("cp.async.wait_group 0;" ::: "memory")

// ===========================================================================
// Mask prep (dtype sniff) — proven
// ===========================================================================
__global__ void mask_prep(const unsigned char* __restrict__ m)
{
    __shared__ int s_cnt[2];
    const int tid = threadIdx.x;
    if (tid < 2) s_cnt[tid] = 0;
    __syncthreads();
    int c1 = 0, c0 = 0;
    for (int i = tid; i < (Bn*Sn)/4; i += blockDim.x) {
        uchar4 v = ((const uchar4*)m)[i];
        if (v.y) c1++;
        if (v.x) c0++;
    }
    atomicAdd(&s_cnt[0], c1);
    atomicAdd(&s_cnt[1], c0);
    __syncthreads();
    const int mode = (s_cnt[0] > 0) ? 0 : ((s_cnt[1] > 0) ? 1 : 2);
    for (int i = tid; i < Bn*Sn; i += blockDim.x) {
        float f;
        if (mode == 0)      f = m[i] ? 1.f : 0.f;
        else if (mode == 1) f = (((const int*)m)[i] != 0) ? 1.f : 0.f;
        else                f = (((const float*)m)[i] != 0.f) ? 1.f : 0.f;
        g_maskf[i] = f;
    }
}

// ===========================================================================
// split_xw: pre-split x (4 MB segments x4) and Wq/Wk/Wv/Wo into bf16 hi/lo.
// grid (1024, 8), 256 threads; each thread one float4 of a 1M-element segment.
// ===========================================================================
__global__ __launch_bounds__(256)
void split_xw(const float* __restrict__ x,
              const float* __restrict__ Wq, const float* __restrict__ Wk,
              const float* __restrict__ Wv, const float* __restrict__ Wo)
{
    const int seg = blockIdx.y;
    const float* src;
    unsigned short *dh, *dl;
    if (seg < 4) {
        src = x + (size_t)seg*MEG;
        dh = g_Xh + (size_t)seg*MEG;
        dl = g_Xl + (size_t)seg*MEG;
    } else {
        const float* ws = (seg==4) ? Wq : (seg==5) ? Wk : (seg==6) ? Wv : Wo;
        src = ws;
        dh = g_Wh + (size_t)(seg-4)*MEG;
        dl = g_Wl + (size_t)(seg-4)*MEG;
    }
    const int i = (blockIdx.x*256 + threadIdx.x) * 4;
    float4 v = *(const float4*)&src[i];
    u32 h0,l0,h1,l1,h2,l2,h3,l3;
    bsplit(v.x,h0,l0); bsplit(v.y,h1,l1); bsplit(v.z,h2,l2); bsplit(v.w,h3,l3);
    *(uint2*)&dh[i] = make_uint2(h0|(h1<<16), h2|(h3<<16));
    *(uint2*)&dl[i] = make_uint2(l0|(l1<<16), l2|(l3<<16));
}

// ===========================================================================
// KV prep (unchanged, proven)
// ===========================================================================
__global__ __launch_bounds__(256)
void kv_prep()
{
    __shared__ float vt[32][65];
    const int tid = threadIdx.x;
    const int bh = blockIdx.z * Hn + blockIdx.y;
    const int s0 = blockIdx.x * 32;
    const float* Ks = g_K + ((size_t)bh*Sn + s0)*Dn;
    const float* Vs = g_V + ((size_t)bh*Sn + s0)*Dn;

    #pragma unroll
    for (int i = 0; i < 2; i++) {
        int f4 = tid + (i << 8);
        int row = f4 >> 4, dim = (f4 & 15) * 4;
        float4 v = *(const float4*)&Ks[row*Dn + dim];
        u32 h0,l0,h1,l1,h2,l2,h3,l3;
        bsplit(v.x,h0,l0); bsplit(v.y,h1,l1); bsplit(v.z,h2,l2); bsplit(v.w,h3,l3);
        size_t o = ((size_t)bh*Sn + s0 + row)*Dn + dim;
        *(uint2*)&g_Kbh[o] = make_uint2(h0|(h1<<16), h2|(h3<<16));
        *(uint2*)&g_Kbl[o] = make_uint2(l0|(l1<<16), l2|(l3<<16));
        float4 w = *(const float4*)&Vs[row*Dn + dim];
        vt[row][dim] = w.x; vt[row][dim+1] = w.y;
        vt[row][dim+2] = w.z; vt[row][dim+3] = w.w;
    }
    __syncthreads();
    #pragma unroll
    for (int i = 0; i < 4; i++) {
        int u = tid + (i << 8);
        int d = u >> 4, j = u & 15;
        float v0 = vt[2*j][d], v1 = vt[2*j+1][d];
        u32 h0,l0,h1,l1;
        bsplit(v0,h0,l0); bsplit(v1,h1,l1);
        size_t o = ((size_t)bh*Dn + d)*Sn + s0 + 2*j;
        *(u32*)&g_Vth[o] = h0 | (h1<<16);
        *(u32*)&g_Vtl[o] = l0 | (l1<<16);
    }
}

// ===========================================================================
// Tensor-core GEMM: pure cp.async + ldmatrix + mma (operands pre-split).
// C[M,N] = A[M,K] * W[N,K]^T + bias; 128x128 tile, BK=32, 8 warps.
// MODE 1: A = x planes, W plane z in {0,1,2}; head-transposed epilogue.
// MODE 0: A = attention-output planes, W plane 3; writes outp.
// ===========================================================================
#define GROWB 80                      // smem row bytes (32 bf16 + 8 pad)
#define PLANE (128*GROWB)             // 10240 B
#define STG (4*PLANE)                 // 40960 B per stage (Ah|Al|Bh|Bl)
#define GEMM_SMEM (2*STG)             // 81920 B

template<int MODE>
__global__ __launch_bounds__(256)
void gemm_mma(const float* __restrict__ bias0, const float* __restrict__ bias1,
              const float* __restrict__ bias2, float* __restrict__ outp)
{
    extern __shared__ char smem[];
    const u32 sbG = smem_u32(smem);
    const int tid = threadIdx.x;
    const int wid = tid >> 5;
    const int lid = tid & 31;
    const int wm  = wid & 3;
    const int wn  = wid >> 2;
    const int m0 = blockIdx.y * 128;
    const int n0 = blockIdx.x * 128;

    const float* bias = bias0;
    float* outq = nullptr;
    const unsigned short *Ah, *Al, *Bh, *Bl;
    if (MODE == 1) {
        int z = blockIdx.z;
        bias = (z==0) ? bias0 : ((z==1) ? bias1 : bias2);
        outq = (z==0) ? g_Q   : ((z==1) ? g_K   : g_V);
        Ah = g_Xh; Al = g_Xl;
        Bh = g_Wh + (size_t)z*MEG; Bl = g_Wl + (size_t)z*MEG;
    } else {
        Ah = g_Ahb; Al = g_Alb;
        Bh = g_Wh + (size_t)3*MEG; Bl = g_Wl + (size_t)3*MEG;
    }

    // per-thread cp.async geometry: 8 chunks of 16B (2048 total per k-tile)
    const unsigned short* srcs[8];
    u32 soff[8];
    #pragma unroll
    for (int i = 0; i < 8; i++) {
        int g = i*256 + tid;
        int plane = g >> 9, idx = g & 511;
        int row = idx >> 2, c16 = idx & 3;
        soff[i] = (u32)plane*PLANE + (u32)row*GROWB + c16*16;
        const unsigned short* base =
            (plane==0) ? Ah : (plane==1) ? Al : (plane==2) ? Bh : Bl;
        int r = ((plane < 2) ? m0 : n0) + row;
        srcs[i] = base + (size_t)r*En + c16*8;
    }

    float c[2][8][4];
    #pragma unroll
    for (int mt = 0; mt < 2; mt++)
        #pragma unroll
        for (int nt = 0; nt < 8; nt++)
            #pragma unroll
            for (int r = 0; r < 4; r++) c[mt][nt][r] = 0.f;

    const u32 nOff8  = ((lid >> 4) & 1) * 8 + (lid & 7);
    const u32 kOff16 = ((lid >> 3) & 1) * 16;
    const u32 aRow0  = (u32)(wm*32 + (lid & 15)) * GROWB + ((lid >> 4) << 4);
    const u32 qrow = lid >> 2;

    // preload k-tile 0
    #pragma unroll
    for (int i = 0; i < 8; i++) {
        CP_ASYNC16(sbG + soff[i], srcs[i]);
        srcs[i] += 32;
    }
    CP_COMMIT();

    const int NKT = En / 32;
    for (int kt = 0; kt < NKT; kt++) {
        CP_WAIT0();
        __syncthreads();
        if (kt + 1 < NKT) {
            const u32 nstg = ((kt + 1) & 1) * STG;
            #pragma unroll
            for (int i = 0; i < 8; i++) {
                CP_ASYNC16(sbG + nstg + soff[i], srcs[i]);
                srcs[i] += 32;
            }
            CP_COMMIT();
        }

        const u32 stgu = sbG + (kt & 1) * STG;
        #pragma unroll
        for (int ks = 0; ks < 2; ks++) {
            const int kb = ks * 32;
            u32 ah[2][4], al[2][4], bh[8][2], bl[8][2];
            #pragma unroll
            for (int mt = 0; mt < 2; mt++) {
                u32 adr = stgu + aRow0 + (u32)(mt*16)*GROWB + kb;
                LDSM_X4(ah[mt][0], ah[mt][1], ah[mt][2], ah[mt][3], adr);
                LDSM_X4(al[mt][0], al[mt][1], al[mt][2], al[mt][3], adr + PLANE);
            }
            #pragma unroll
            for (int p = 0; p < 4; p++) {
                u32 adr = stgu + 2*PLANE
                        + (u32)(wn*64 + p*16 + nOff8)*GROWB + kOff16 + kb;
                LDSM_X4(bh[2*p][0], bh[2*p][1], bh[2*p+1][0], bh[2*p+1][1], adr);
                LDSM_X4(bl[2*p][0], bl[2*p][1], bl[2*p+1][0], bl[2*p+1][1],
                        adr + PLANE);
            }
            #pragma unroll
            for (int mt = 0; mt < 2; mt++)
                #pragma unroll
                for (int nt = 0; nt < 8; nt++) {
                    mma_bf16(c[mt][nt], ah[mt][0], ah[mt][1], ah[mt][2], ah[mt][3],
                             bh[nt][0], bh[nt][1]);
                    mma_bf16(c[mt][nt], ah[mt][0], ah[mt][1], ah[mt][2], ah[mt][3],
                             bl[nt][0], bl[nt][1]);
                    mma_bf16(c[mt][nt], al[mt][0], al[mt][1], al[mt][2], al[mt][3],
                             bh[nt][0], bh[nt][1]);
                }
        }
        __syncthreads();
    }

    #pragma unroll
    for (int mt = 0; mt < 2; mt++) {
        #pragma unroll
        for (int nt = 0; nt < 8; nt++) {
            int row = m0 + wm*32 + mt*16 + qrow;
            int col = n0 + wn*64 + nt*8 + (lid & 3)*2;
            float b0 = bias[col], b1 = bias[col + 1];
            float2 lo = make_float2(c[mt][nt][0] + b0, c[mt][nt][1] + b1);
            float2 hi = make_float2(c[mt][nt][2] + b0, c[mt][nt][3] + b1);
            if (MODE == 1) {
                int bb = row >> 11;
                int h  = col >> 6;
                int d  = col & 63;
                size_t base = ((size_t)(bb*Hn + h)*Sn) * Dn + d;
                *(float2*)&outq[base + (size_t)(row & (Sn-1))*Dn]       = lo;
                *(float2*)&outq[base + (size_t)((row & (Sn-1)) + 8)*Dn] = hi;
            } else {
                *(float2*)&outp[(size_t)row*En + col]       = lo;
                *(float2*)&outp[(size_t)(row + 8)*En + col] = hi;
            }
        }
    }
}

// ===========================================================================
// Tensor-core flash attention (R12 structure, 2 CTAs/SM).
// Epilogue now writes bf16 hi/lo planes (g_Ahb/g_Alb) for gemm<0>.
// ===========================================================================
#define SQB 144
#define QPL (64*SQB)
#define OFF_QL QPL
#define OFF_STAGE (2*QPL)
#define SKL QPL
#define SVH (2*QPL)
#define SVL (3*QPL)
#define STAGE_SZ (4*QPL)
#define OFF_MS (OFF_STAGE + 2*STAGE_SZ)
#define ATT_SMEM (OFF_MS + 512)

__global__ __launch_bounds__(128, 2)
void attn_tc()
{
    extern __shared__ char sm[];
    const u32 sb = smem_u32(sm);
    const int tid = threadIdx.x;
    const int wid = tid >> 5, lid = tid & 31;
    const int qr = lid >> 2, qc = lid & 3;
    const int qt = blockIdx.x, h = blockIdx.y, b = blockIdx.z;
    const int bh = b*Hn + h;

    const float* Qg = g_Q + ((size_t)bh*Sn + qt*64)*Dn;
    const float* mk = g_maskf + b*Sn;
    const unsigned short* Khg = g_Kbh + (size_t)bh*Sn*Dn;
    const unsigned short* Klg = g_Kbl + (size_t)bh*Sn*Dn;
    const unsigned short* Vhg = g_Vth + (size_t)bh*Dn*Sn;
    const unsigned short* Vlg = g_Vtl + (size_t)bh*Dn*Sn;
    float* mS = (float*)(sm + OFF_MS);

    #pragma unroll
    for (int i = 0; i < 8; i++) {
        int f4 = tid + (i << 7);
        int row = f4 >> 4, dim = (f4 & 15) << 2;
        float4 v = *(const float4*)&Qg[row*Dn + dim];
        v.x *= 0.125f; v.y *= 0.125f; v.z *= 0.125f; v.w *= 0.125f;
        u32 h0,l0,h1,l1,h2,l2,h3,l3;
        bsplit(v.x,h0,l0); bsplit(v.y,h1,l1); bsplit(v.z,h2,l2); bsplit(v.w,h3,l3);
        *(uint2*)(sm + row*SQB + dim*2)          = make_uint2(h0|(h1<<16), h2|(h3<<16));
        *(uint2*)(sm + OFF_QL + row*SQB + dim*2) = make_uint2(l0|(l1<<16), l2|(l3<<16));
    }

    auto issue = [&](int kt, int st) {
        const u32 stg = sb + OFF_STAGE + st*STAGE_SZ;
        #pragma unroll
        for (int i = 0; i < 16; i++) {
            int c = tid + (i << 7);
            if (c < 1024) {
                int pl = c >> 9, idx = c & 511;
                int row = idx >> 3, col = idx & 7;
                const unsigned short* src = (pl ? Klg : Khg)
                    + (size_t)(kt*64 + row)*Dn + col*8;
                CP_ASYNC16(stg + pl*SKL + row*SQB + col*16, src);
            } else {
                int c2 = c - 1024;
                int pl = c2 >> 9, idx = c2 & 511;
                int d = idx >> 3, col = idx & 7;
                const unsigned short* src = (pl ? Vlg : Vhg)
                    + (size_t)d*Sn + kt*64 + col*8;
                CP_ASYNC16(stg + SVH + pl*(SVL-SVH) + d*SQB + col*16, src);
            }
        }
        if (tid < 64) mS[st*64 + tid] = mk[kt*64 + tid];
        CP_COMMIT();
    };

    float m0 = -INFINITY, m1 = -INFINITY, l0 = 0.f, l1 = 0.f;
    float acc[8][4];
    #pragma unroll
    for (int nt = 0; nt < 8; nt++)
        #pragma unroll
        for (int r = 0; r < 4; r++) acc[nt][r] = 0.f;

    issue(0, 0);

    const u32 nOff8  = ((lid >> 4) & 1) * 8 + (lid & 7);
    const u32 kOff16 = ((lid >> 3) & 1) * 16;
    const u32 qAhi = sb + (u32)(wid*16 + (lid & 15))*SQB + ((lid >> 4) << 4);

    for (int kt = 0; kt < Sn/64; kt++) {
        const int st = kt & 1;
        CP_WAIT0();
        __syncthreads();
        if (kt + 1 < Sn/64) issue(kt + 1, 1 - st);

        const u32 KHu = sb + OFF_STAGE + st*STAGE_SZ;
        const u32 KLu = KHu + SKL;
        const u32 VHu = KHu + SVH;
        const u32 VLu = KHu + SVL;

        float sc[8][4];
        #pragma unroll
        for (int nt = 0; nt < 8; nt++)
            #pragma unroll
            for (int r = 0; r < 4; r++) sc[nt][r] = 0.f;

        #pragma unroll
        for (int ks = 0; ks < 4; ks++) {
            u32 ah[4], al[4];
            LDSM_X4(ah[0], ah[1], ah[2], ah[3], qAhi + ks*32);
            LDSM_X4(al[0], al[1], al[2], al[3], qAhi + OFF_QL + ks*32);
            #pragma unroll
            for (int p = 0; p < 4; p++) {
                u32 badr = (u32)(p*16 + nOff8)*SQB + kOff16 + ks*32;
                u32 bh0, bh1, bh2, bh3, bl0, bl1, bl2, bl3;
                LDSM_X4(bh0, bh1, bh2, bh3, KHu + badr);
                LDSM_X4(bl0, bl1, bl2, bl3, KLu + badr);
                mma_bf16(sc[2*p],   ah[0], ah[1], ah[2], ah[3], bh0, bh1);
                mma_bf16(sc[2*p],   ah[0], ah[1], ah[2], ah[3], bl0, bl1);
                mma_bf16(sc[2*p],   al[0], al[1], al[2], al[3], bh0, bh1);
                mma_bf16(sc[2*p+1], ah[0], ah[1], ah[2], ah[3], bh2, bh3);
                mma_bf16(sc[2*p+1], ah[0], ah[1], ah[2], ah[3], bl2, bl3);
                mma_bf16(sc[2*p+1], al[0], al[1], al[2], al[3], bh2, bh3);
            }
        }

        const float* msk = mS + st*64;
        #pragma unroll
        for (int nt = 0; nt < 8; nt++) {
            int c0 = nt*8 + qc*2;
            if (msk[c0]   != 0.f) { sc[nt][0] = -1e9f; sc[nt][2] = -1e9f; }
            if (msk[c0+1] != 0.f) { sc[nt][1] = -1e9f; sc[nt][3] = -1e9f; }
        }

        float mx0 = -INFINITY, mx1 = -INFINITY;
        #pragma unroll
        for (int nt = 0; nt < 8; nt++) {
            mx0 = fmaxf(mx0, fmaxf(sc[nt][0], sc[nt][1]));
            mx1 = fmaxf(mx1, fmaxf(sc[nt][2], sc[nt][3]));
        }
        mx0 = fmaxf(mx0, __shfl_xor_sync(0xffffffffu, mx0, 1));
        mx0 = fmaxf(mx0, __shfl_xor_sync(0xffffffffu, mx0, 2));
        mx1 = fmaxf(mx1, __shfl_xor_sync(0xffffffffu, mx1, 1));
        mx1 = fmaxf(mx1, __shfl_xor_sync(0xffffffffu, mx1, 2));
        float mn0 = fmaxf(m0, mx0), mn1 = fmaxf(m1, mx1);
        float fs0 = __expf(m0 - mn0), fs1 = __expf(m1 - mn1);
        m0 = mn0; m1 = mn1;

        float ps0 = 0.f, ps1 = 0.f;
        #pragma unroll
        for (int nt = 0; nt < 8; nt++) {
            float p0 = __expf(sc[nt][0] - mn0);
            float p1 = __expf(sc[nt][1] - mn0);
            float p2 = __expf(sc[nt][2] - mn1);
            float p3 = __expf(sc[nt][3] - mn1);
            ps0 += p0 + p1; ps1 += p2 + p3;
            sc[nt][0] = p0; sc[nt][1] = p1; sc[nt][2] = p2; sc[nt][3] = p3;
        }
        ps0 += __shfl_xor_sync(0xffffffffu, ps0, 1);
        ps0 += __shfl_xor_sync(0xffffffffu, ps0, 2);
        ps1 += __shfl_xor_sync(0xffffffffu, ps1, 1);
        ps1 += __shfl_xor_sync(0xffffffffu, ps1, 2);
        l0 = l0*fs0 + ps0;
        l1 = l1*fs1 + ps1;

        #pragma unroll
        for (int nt = 0; nt < 8; nt++) {
            acc[nt][0] *= fs0; acc[nt][1] *= fs0;
            acc[nt][2] *= fs1; acc[nt][3] *= fs1;
        }

        u32 pah[4][4], pal[4][4];
        #pragma unroll
        for (int ksl = 0; ksl < 4; ksl++) {
            psplit2(sc[2*ksl][0],   sc[2*ksl][1],   pah[ksl][0], pal[ksl][0]);
            psplit2(sc[2*ksl][2],   sc[2*ksl][3],   pah[ksl][1], pal[ksl][1]);
            psplit2(sc[2*ksl+1][0], sc[2*ksl+1][1], pah[ksl][2], pal[ksl][2]);
            psplit2(sc[2*ksl+1][2], sc[2*ksl+1][3], pah[ksl][3], pal[ksl][3]);
        }
        #pragma unroll
        for (int ksl = 0; ksl < 4; ksl++) {
            #pragma unroll
            for (int p = 0; p < 4; p++) {
                u32 vadr = (u32)(p*16 + nOff8)*SQB + kOff16 + ksl*32;
                u32 vh0, vh1, vh2, vh3, vl0, vl1, vl2, vl3;
                LDSM_X4(vh0, vh1, vh2, vh3, VHu + vadr);
                LDSM_X4(vl0, vl1, vl2, vl3, VLu + vadr);
                mma_bf16(acc[2*p], pah[ksl][0], pah[ksl][1], pah[ksl][2],
                         pah[ksl][3], vh0, vh1);
                mma_bf16(acc[2*p], pal[ksl][0], pal[ksl][1], pal[ksl][2],
                         pal[ksl][3], vh0, vh1);
                mma_bf16(acc[2*p], pah[ksl][0], pah[ksl][1], pah[ksl][2],
                         pah[ksl][3], vl0, vl1);
                mma_bf16(acc[2*p+1], pah[ksl][0], pah[ksl][1], pah[ksl][2],
                         pah[ksl][3], vh2, vh3);
                mma_bf16(acc[2*p+1], pal[ksl][0], pal[ksl][1], pal[ksl][2],
                         pal[ksl][3], vh2, vh3);
                mma_bf16(acc[2*p+1], pah[ksl][0], pah[ksl][1], pah[ksl][2],
                         pah[ksl][3], vl2, vl3);
            }
        }
    }

    // ---- epilogue: normalize, split to bf16 hi/lo planes for gemm<0> ----
    float inv0 = 1.f / l0, inv1 = 1.f / l1;
    int row0 = qt*64 + wid*16 + qr;
    #pragma unroll
    for (int nt = 0; nt < 8; nt++) {
        int d = h*64 + nt*8 + qc*2;
        size_t o0 = ((size_t)(b*Sn + row0))*En + d;
        size_t o1 = ((size_t)(b*Sn + row0 + 8))*En + d;
        u32 hp, lp;
        psplit2(acc[nt][0]*inv0, acc[nt][1]*inv0, hp, lp);
        *(u32*)&g_Ahb[o0] = hp;
        *(u32*)&g_Alb[o0] = lp;
        psplit2(acc[nt][2]*inv1, acc[nt][3]*inv1, hp, lp);
        *(u32*)&g_Ahb[o1] = hp;
        *(u32*)&g_Alb[o1] = lp;
    }
}

// ---------------------------------------------------------------------------
extern "C" void kernel_launch(void* const* d_in, const int* in_sizes, int n_in,
                              void* d_out, int out_size)
{
    const float* x  = (const float*)d_in[0];
    const unsigned char* mask = (const unsigned char*)d_in[1];
    const float* Wq = (const float*)d_in[2];
    const float* bq = (const float*)d_in[3];
    const float* Wk = (const float*)d_in[4];
    const float* bk = (const float*)d_in[5];
    const float* Wv = (const float*)d_in[6];
    const float* bv = (const float*)d_in[7];
    const float* Wo = (const float*)d_in[8];
    const float* bo = (const float*)d_in[9];
    float* out = (float*)d_out;

    cudaFuncSetAttribute(gemm_mma<1>,
                         cudaFuncAttributeMaxDynamicSharedMemorySize, GEMM_SMEM);
    cudaFuncSetAttribute(gemm_mma<0>,
                         cudaFuncAttributeMaxDynamicSharedMemorySize, GEMM_SMEM);
    cudaFuncSetAttribute(attn_tc,
                         cudaFuncAttributeMaxDynamicSharedMemorySize, ATT_SMEM);

    mask_prep<<<1, 256>>>(mask);
    split_xw<<<dim3(1024, 8), 256>>>(x, Wq, Wk, Wv, Wo);

    gemm_mma<1><<<dim3(En/128, Mn/128, 3), 256, GEMM_SMEM>>>(bq, bk, bv, nullptr);

    kv_prep<<<dim3(Sn/32, Hn, Bn), 256>>>();

    attn_tc<<<dim3(Sn/64, Hn, Bn), 128, ATT_SMEM>>>();

    gemm_mma<0><<<dim3(En/128, Mn/128, 1), 256, GEMM_SMEM>>>(bo, nullptr, nullptr, out);
}